// round 6
// baseline (speedup 1.0000x reference)
#include <cuda_runtime.h>
#include <math.h>

// Problem shape (fixed by the dataset)
#define W_ 160
#define H_ 128
#define C_ 32
#define G_ 8
#define D_ 48
#define S_ 2
#define HW_ (H_ * W_)

#define SNAP_ 3e-5f
#define LOG2E_ 1.44269504088896340736f
#define MAGIC_ 12582912.0f  // 1.5 * 2^23
#define KEXP_ (127 - 0x4B400000)

// Scratch (no cudaMalloc allowed)
__device__ float4 g_ref4[G_ * HW_];          // ref softmax, channel-packed
__device__ float4 g_src4[S_ * G_ * HW_];     // src features, channel-packed
__device__ float g_rot[S_][9];
__device__ float g_trans[S_][3];
__device__ float g_w1[G_];
__device__ float g_aff[4];  // s1, c1, w2, b2

typedef unsigned long long u64;

__device__ __forceinline__ float ex2f(float x) {
    float y; asm("ex2.approx.f32 %0, %1;" : "=f"(y) : "f"(x)); return y;
}
__device__ __forceinline__ float rcpf(float x) {
    float y; asm("rcp.approx.f32 %0, %1;" : "=f"(y) : "f"(x)); return y;
}
__device__ __forceinline__ u64 pk2(float a, float b) {
    u64 r; asm("mov.b64 %0, {%1, %2};" : "=l"(r) : "f"(a), "f"(b)); return r;
}
__device__ __forceinline__ void upk2(u64 v, float& a, float& b) {
    asm("mov.b64 {%0, %1}, %2;" : "=f"(a), "=f"(b) : "l"(v));
}
__device__ __forceinline__ u64 fma2(u64 a, u64 b, u64 c) {
    u64 r; asm("fma.rn.f32x2 %0, %1, %2, %3;" : "=l"(r) : "l"(a), "l"(b), "l"(c)); return r;
}
__device__ __forceinline__ u64 mul2(u64 a, u64 b) {
    u64 r; asm("mul.rn.f32x2 %0, %1, %2;" : "=l"(r) : "l"(a), "l"(b)); return r;
}
__device__ __forceinline__ u64 add2(u64 a, u64 b) {
    u64 r; asm("add.rn.f32x2 %0, %1, %2;" : "=l"(r) : "l"(a), "l"(b)); return r;
}

// Packed exp2 of a pair: magic-number range reduction + deg-4 Taylor poly.
// Valid for |a| < ~60 (plenty: |a| <= ~10 here).
__device__ __forceinline__ u64 exp2_pair(u64 a01, u64 MAG2, u64 NEG1,
                                         u64 C4, u64 C3, u64 C2, u64 C1, u64 C0) {
    u64 t01 = add2(a01, MAG2);                 // round(a) in low mantissa bits
    uint2 tp = *reinterpret_cast<uint2*>(&t01);
    u64 i01 = add2(t01, pk2(-MAGIC_, -MAGIC_)); // (float)round(a) exactly
    u64 f01 = fma2(i01, NEG1, a01);            // frac in [-0.5, 0.5]
    u64 p = fma2(f01, C4, C3);
    p = fma2(f01, p, C2);
    p = fma2(f01, p, C1);
    p = fma2(f01, p, C0);
    unsigned b0 = (tp.x + (unsigned)KEXP_) << 23;
    unsigned b1 = (tp.y + (unsigned)KEXP_) << 23;
    u64 s01 = ((u64)b1 << 32) | b0;            // packed scale pair (bit concat)
    return mul2(p, s01);
}

// ---------------------------------------------------------------------------
// Prep (single fused kernel): params (thread 0) + src transpose + ref softmax
// ---------------------------------------------------------------------------
#define T1_ (S_ * G_ * HW_)
#define T2_ (T1_ + G_ * HW_)

__global__ __launch_bounds__(256) void prep_all_kernel(
    const float* __restrict__ ref_feature,
    const float* __restrict__ srcF,
    const float* __restrict__ ref_proj,
    const float* __restrict__ src_projs,
    const float* __restrict__ w1,
    const float* __restrict__ bn_gamma,
    const float* __restrict__ bn_beta,
    const float* __restrict__ bn_mean,
    const float* __restrict__ bn_var,
    const float* __restrict__ w2,
    const float* __restrict__ b2) {
    int t = blockIdx.x * blockDim.x + threadIdx.x;

    if (t == 0) {
        float a[4][8];
        for (int i = 0; i < 4; i++)
            for (int j = 0; j < 4; j++) {
                a[i][j] = ref_proj[i * 4 + j];
                a[i][4 + j] = (i == j) ? 1.0f : 0.0f;
            }
        for (int col = 0; col < 4; col++) {
            int piv = col;
            float best = fabsf(a[col][col]);
            for (int r = col + 1; r < 4; r++) {
                float v = fabsf(a[r][col]);
                if (v > best) { best = v; piv = r; }
            }
            if (piv != col)
                for (int j = 0; j < 8; j++) {
                    float tmp = a[col][j]; a[col][j] = a[piv][j]; a[piv][j] = tmp;
                }
            float inv = 1.0f / a[col][col];
            for (int j = 0; j < 8; j++) a[col][j] *= inv;
            for (int r = 0; r < 4; r++) {
                if (r == col) continue;
                float f = a[r][col];
                for (int j = 0; j < 8; j++) a[r][j] -= f * a[col][j];
            }
        }
        for (int s = 0; s < S_; s++) {
            const float* sp = src_projs + s * 16;
            for (int i = 0; i < 3; i++) {
                float pr[4];
                for (int j = 0; j < 4; j++) {
                    float acc = 0.0f;
                    for (int k = 0; k < 4; k++)
                        acc += sp[i * 4 + k] * a[k][4 + j];
                    pr[j] = acc;
                }
                g_rot[s][i * 3 + 0] = pr[0];
                g_rot[s][i * 3 + 1] = pr[1];
                g_rot[s][i * 3 + 2] = pr[2];
                g_trans[s][i] = pr[3];
            }
        }
        for (int g = 0; g < G_; g++) g_w1[g] = w1[g];
        float s1 = bn_gamma[0] * rsqrtf(bn_var[0] + 1e-5f);
        float c1 = bn_beta[0] - bn_mean[0] * s1;
        g_aff[0] = s1;
        g_aff[1] = c1;
        g_aff[2] = w2[0];
        g_aff[3] = b2[0];
    }

    if (t < T1_) {
        int p = t % HW_;
        int sg = t / HW_;
        int s = sg / G_;
        int g = sg % G_;
        const float* b = srcF + (s * C_ + 4 * g) * HW_ + p;
        float4 v;
        v.x = b[0];
        v.y = b[HW_];
        v.z = b[2 * HW_];
        v.w = b[3 * HW_];
        g_src4[sg * HW_ + p] = v;
    } else if (t < T2_) {
        int u = t - T1_;
        int p = u % HW_;
        int g = u / HW_;
        const float* b = ref_feature + (g * 4) * HW_ + p;
        float e0 = __expf(b[0]);
        float e1 = __expf(b[HW_]);
        float e2 = __expf(b[2 * HW_]);
        float e3 = __expf(b[3 * HW_]);
        float is = __fdividef(1.0f, (e0 + e1) + (e2 + e3));
        float4 o;
        o.x = e0 * is;
        o.y = e1 * is;
        o.z = e2 * is;
        o.w = e3 * is;
        g_ref4[g * HW_ + p] = o;
    }
}

// ---------------------------------------------------------------------------
// Main fused kernel. Grid (W/32, H/4, D); block (32, 8).
// Source 0 softmax uses MUFU ex2; source 1 uses packed polynomial exp2 on the
// FMA pipe (pipe rebalance). One reciprocal per group serves both sources.
// ---------------------------------------------------------------------------
__global__ __launch_bounds__(256, 4) void fuse_kernel(const float* __restrict__ depths,
                                                      float* __restrict__ out) {
    __shared__ float s_lin[2][4][32][2];  // [half][row][lane][src]

    int tx = threadIdx.x;
    int ty = threadIdx.y;
    int row = ty & 3;
    int h = ty >> 2;                      // group half (warp-uniform)
    int x = blockIdx.x * 32 + tx;
    int y = blockIdx.y * 4 + row;
    int d = blockIdx.z;
    int p = y * W_ + x;
    float xf = (float)x, yf = (float)y;
    float depth = __ldg(depths + d);

    // Packed poly constants (deg-4 Taylor of 2^f, f in [-0.5, 0.5])
    const u64 C0 = pk2(1.0f, 1.0f);
    const u64 C1 = pk2(0.69314718f, 0.69314718f);
    const u64 C2 = pk2(0.24022651f, 0.24022651f);
    const u64 C3 = pk2(0.05550411f, 0.05550411f);
    const u64 C4 = pk2(0.00961813f, 0.00961813f);
    const u64 MAG2 = pk2(MAGIC_, MAGIC_);
    const u64 NEG1 = pk2(-1.0f, -1.0f);

    // Per-source geometry
    int off0[S_], dxs[S_], dys[S_];
    u64 w00p[S_], w01p[S_], w10p[S_], w11p[S_];
    float wys[S_];
#pragma unroll
    for (int s = 0; s < S_; s++) {
        float X = fmaf(fmaf(g_rot[s][0], xf, fmaf(g_rot[s][1], yf, g_rot[s][2])), depth, g_trans[s][0]);
        float Y = fmaf(fmaf(g_rot[s][3], xf, fmaf(g_rot[s][4], yf, g_rot[s][5])), depth, g_trans[s][1]);
        float Z = fmaf(fmaf(g_rot[s][6], xf, fmaf(g_rot[s][7], yf, g_rot[s][8])), depth, g_trans[s][2]);
        float iz = __fdividef(1.0f, Z);
        float px = X * iz;
        float py = Y * iz;
        float x0f = floorf(px), y0f = floorf(py);
        float wx = px - x0f, wy = py - y0f;
        if (wx < SNAP_) { wx = 0.0f; }
        else if (wx > 1.0f - SNAP_) { wx = 0.0f; x0f += 1.0f; }
        if (wy < SNAP_) { wy = 0.0f; }
        else if (wy > 1.0f - SNAP_) { wy = 0.0f; y0f += 1.0f; }
        float vx0 = (x0f >= 0.0f && x0f <= (float)(W_ - 1)) ? LOG2E_ : 0.0f;
        float vx1 = (x0f + 1.0f >= 0.0f && x0f + 1.0f <= (float)(W_ - 1)) ? LOG2E_ : 0.0f;
        float vy0 = (y0f >= 0.0f && y0f <= (float)(H_ - 1)) ? 1.0f : 0.0f;
        float vy1 = (y0f + 1.0f >= 0.0f && y0f + 1.0f <= (float)(H_ - 1)) ? 1.0f : 0.0f;
        float wl = (1.0f - wx) * vx0, wr = wx * vx1;   // include log2e
        float wt = (1.0f - wy) * vy0, wb = wy * vy1;
        float w00 = wl * wt, w01 = wr * wt;
        float w10 = wl * wb, w11 = wr * wb;
        w00p[s] = pk2(w00, w00);
        w01p[s] = pk2(w01, w01);
        w10p[s] = pk2(w10, w10);
        w11p[s] = pk2(w11, w11);
        int xi0 = min(max((int)x0f, 0), W_ - 1);
        int yi0 = min(max((int)y0f, 0), H_ - 1);
        int xi1 = min(max((int)x0f + 1, 0), W_ - 1);
        int yi1 = min(max((int)y0f + 1, 0), H_ - 1);
        off0[s] = yi0 * W_ + xi0;
        dxs[s] = xi1 - xi0;
        dys[s] = (yi1 - yi0) * W_;
        wys[s] = wy;
    }

    float v0r[4], v1r[4];
    float lin0 = 0.0f, lin1 = 0.0f;
    int gbase = h * 4;
    bool bottom = (wys[0] + wys[1]) > 0.0f;  // warp-uniform

    const ulonglong2* sb0 = (const ulonglong2*)(g_src4 + (0 * G_ + gbase) * HW_ + off0[0]);
    const ulonglong2* sb1 = (const ulonglong2*)(g_src4 + (1 * G_ + gbase) * HW_ + off0[1]);
    const float4* rp = g_ref4 + gbase * HW_ + p;

#pragma unroll
    for (int j = 0; j < 4; j++) {
        float4 r = rp[j * HW_];
        u64 rr01 = pk2(r.x, r.y);
        u64 rr23 = pk2(r.z, r.w);

        // ---- source 0 blend ----
        const ulonglong2* q0 = sb0 + j * HW_;
        ulonglong2 qa0 = q0[0];
        ulonglong2 qb0 = q0[dxs[0]];
        u64 A01 = fma2(w00p[0], qa0.x, mul2(w01p[0], qb0.x));
        u64 A23 = fma2(w00p[0], qa0.y, mul2(w01p[0], qb0.y));
        // ---- source 1 blend ----
        const ulonglong2* q1 = sb1 + j * HW_;
        ulonglong2 qa1 = q1[0];
        ulonglong2 qb1 = q1[dxs[1]];
        u64 B01 = fma2(w00p[1], qa1.x, mul2(w01p[1], qb1.x));
        u64 B23 = fma2(w00p[1], qa1.y, mul2(w01p[1], qb1.y));
        if (bottom) {
            ulonglong2 qc0 = q0[dys[0]];
            ulonglong2 qd0 = q0[dys[0] + dxs[0]];
            A01 = fma2(w10p[0], qc0.x, fma2(w11p[0], qd0.x, A01));
            A23 = fma2(w10p[0], qc0.y, fma2(w11p[0], qd0.y, A23));
            ulonglong2 qc1 = q1[dys[1]];
            ulonglong2 qd1 = q1[dys[1] + dxs[1]];
            B01 = fma2(w10p[1], qc1.x, fma2(w11p[1], qd1.x, B01));
            B23 = fma2(w10p[1], qc1.y, fma2(w11p[1], qd1.y, B23));
        }

        // ---- source 0 softmax-dot (MUFU ex2) ----
        float a0, a1, a2, a3;
        upk2(A01, a0, a1);
        upk2(A23, a2, a3);
        float e0 = ex2f(a0), e1 = ex2f(a1);
        float e2 = ex2f(a2), e3 = ex2f(a3);
        float ss0 = (e0 + e1) + (e2 + e3);
        float num0 = fmaf(e0, r.x, fmaf(e1, r.y, fmaf(e2, r.z, e3 * r.w)));

        // ---- source 1 softmax-dot (packed poly exp2 on FMA pipe) ----
        u64 E01 = exp2_pair(B01, MAG2, NEG1, C4, C3, C2, C1, C0);
        u64 E23 = exp2_pair(B23, MAG2, NEG1, C4, C3, C2, C1, C0);
        u64 sum2 = add2(E01, E23);
        float su, sv;
        upk2(sum2, su, sv);
        float ss1 = su + sv;
        u64 n2 = fma2(E23, rr23, mul2(E01, rr01));
        float nu, nv;
        upk2(n2, nu, nv);
        float num1 = nu + nv;

        // ---- merged reciprocal ----
        float R = rcpf(ss0 * ss1);
        float vv0 = (num0 * ss1) * R;
        float vv1 = (num1 * ss0) * R;
        v0r[j] = vv0;
        v1r[j] = vv1;
        float w1g = g_w1[gbase + j];
        lin0 = fmaf(w1g, vv0, lin0);
        lin1 = fmaf(w1g, vv1, lin1);
    }

    // Exchange partial lin sums across the two group-halves
    s_lin[h][row][tx][0] = lin0;
    s_lin[h][row][tx][1] = lin1;
    __syncthreads();
    float L0 = s_lin[0][row][tx][0] + s_lin[1][row][tx][0];
    float L1 = s_lin[0][row][tx][1] + s_lin[1][row][tx][1];

    float s1 = g_aff[0], c1 = g_aff[1], w2c = g_aff[2], b2c = g_aff[3];
    float bn0 = fmaf(L0, s1, c1);
    float bn1 = fmaf(L1, s1, c1);
    float ac0 = fmaf(fmaxf(bn0, 0.0f), w2c, b2c);
    float ac1 = fmaf(fmaxf(bn1, 0.0f), w2c, b2c);
    float wgt0 = rcpf(1.0f + __expf(-ac0));
    float wgt1 = rcpf(1.0f + __expf(-ac1));
    float iw = rcpf(wgt0 + wgt1);

    float* op = out + (gbase * D_ + d) * HW_ + p;
#pragma unroll
    for (int j = 0; j < 4; j++) {
        op[j * (D_ * HW_)] = (wgt0 * v0r[j] + wgt1 * v1r[j]) * iw;
    }
}

// ---------------------------------------------------------------------------
// Launch
// ---------------------------------------------------------------------------
extern "C" void kernel_launch(void* const* d_in, const int* in_sizes, int n_in,
                              void* d_out, int out_size) {
    const float* ref_feature = (const float*)d_in[0];
    const float* src_features = (const float*)d_in[1];
    const float* ref_proj = (const float*)d_in[2];
    const float* src_projs = (const float*)d_in[3];
    const float* depth_hypos = (const float*)d_in[4];
    const float* w1 = (const float*)d_in[5];
    const float* bn_gamma = (const float*)d_in[6];
    const float* bn_beta = (const float*)d_in[7];
    const float* bn_mean = (const float*)d_in[8];
    const float* bn_var = (const float*)d_in[9];
    const float* w2 = (const float*)d_in[10];
    const float* b2 = (const float*)d_in[11];
    float* out = (float*)d_out;

    prep_all_kernel<<<(T2_ + 255) / 256, 256>>>(
        ref_feature, src_features, ref_proj, src_projs, w1, bn_gamma, bn_beta,
        bn_mean, bn_var, w2, b2);

    dim3 grid(W_ / 32, H_ / 4, D_);
    dim3 block(32, 8);
    fuse_kernel<<<grid, block>>>(depth_hypos, out);
}

// round 7
// speedup vs baseline: 1.0096x; 1.0096x over previous
#include <cuda_runtime.h>
#include <math.h>

// Problem shape (fixed by the dataset)
#define W_ 160
#define H_ 128
#define C_ 32
#define G_ 8
#define D_ 48
#define S_ 2
#define HW_ (H_ * W_)

#define SNAP_ 3e-5f
#define LOG2E_ 1.44269504088896340736f

// Scratch (no cudaMalloc allowed)
__device__ float4 g_ref4[G_ * HW_];          // ref softmax, channel-packed
__device__ float4 g_src4[S_ * G_ * HW_];     // src features, channel-packed
__device__ float g_rot[S_][9];
__device__ float g_trans[S_][3];
__device__ float g_w1[G_];
__device__ float g_aff[4];  // s1, c1, w2, b2
// Fast-geometry tables (valid when g_fast != 0): per (s,d) integer shift and
// snap-folded bilinear weights (log2e included).
__device__ int    g_fast;
__device__ int    g_sdk[S_][D_];
__device__ float2 g_sdw[S_][D_];

typedef unsigned long long u64;

__device__ __forceinline__ float ex2f(float x) {
    float y; asm("ex2.approx.f32 %0, %1;" : "=f"(y) : "f"(x)); return y;
}
__device__ __forceinline__ u64 pk2(float a, float b) {
    u64 r; asm("mov.b64 %0, {%1, %2};" : "=l"(r) : "f"(a), "f"(b)); return r;
}
__device__ __forceinline__ void upk2(u64 v, float& a, float& b) {
    asm("mov.b64 {%0, %1}, %2;" : "=f"(a), "=f"(b) : "l"(v));
}
__device__ __forceinline__ u64 fma2(u64 a, u64 b, u64 c) {
    u64 r; asm("fma.rn.f32x2 %0, %1, %2, %3;" : "=l"(r) : "l"(a), "l"(b), "l"(c)); return r;
}
__device__ __forceinline__ u64 mul2(u64 a, u64 b) {
    u64 r; asm("mul.rn.f32x2 %0, %1, %2;" : "=l"(r) : "l"(a), "l"(b)); return r;
}

// ---------------------------------------------------------------------------
// Prep (single fused kernel): params + fast-geometry tables (thread 0) +
// src transpose + ref softmax
// ---------------------------------------------------------------------------
#define T1_ (S_ * G_ * HW_)
#define T2_ (T1_ + G_ * HW_)

__global__ __launch_bounds__(256) void prep_all_kernel(
    const float* __restrict__ ref_feature,
    const float* __restrict__ srcF,
    const float* __restrict__ ref_proj,
    const float* __restrict__ src_projs,
    const float* __restrict__ depths,
    const float* __restrict__ w1,
    const float* __restrict__ bn_gamma,
    const float* __restrict__ bn_beta,
    const float* __restrict__ bn_mean,
    const float* __restrict__ bn_var,
    const float* __restrict__ w2,
    const float* __restrict__ b2) {
    int t = blockIdx.x * blockDim.x + threadIdx.x;

    if (t == 0) {
        float a[4][8];
        for (int i = 0; i < 4; i++)
            for (int j = 0; j < 4; j++) {
                a[i][j] = ref_proj[i * 4 + j];
                a[i][4 + j] = (i == j) ? 1.0f : 0.0f;
            }
        for (int col = 0; col < 4; col++) {
            int piv = col;
            float best = fabsf(a[col][col]);
            for (int r = col + 1; r < 4; r++) {
                float v = fabsf(a[r][col]);
                if (v > best) { best = v; piv = r; }
            }
            if (piv != col)
                for (int j = 0; j < 8; j++) {
                    float tmp = a[col][j]; a[col][j] = a[piv][j]; a[piv][j] = tmp;
                }
            float inv = 1.0f / a[col][col];
            for (int j = 0; j < 8; j++) a[col][j] *= inv;
            for (int r = 0; r < 4; r++) {
                if (r == col) continue;
                float f = a[r][col];
                for (int j = 0; j < 8; j++) a[r][j] -= f * a[col][j];
            }
        }
        for (int s = 0; s < S_; s++) {
            const float* sp = src_projs + s * 16;
            for (int i = 0; i < 3; i++) {
                float pr[4];
                for (int j = 0; j < 4; j++) {
                    float acc = 0.0f;
                    for (int k = 0; k < 4; k++)
                        acc += sp[i * 4 + k] * a[k][4 + j];
                    pr[j] = acc;
                }
                g_rot[s][i * 3 + 0] = pr[0];
                g_rot[s][i * 3 + 1] = pr[1];
                g_rot[s][i * 3 + 2] = pr[2];
                g_trans[s][i] = pr[3];
            }
        }
        for (int g = 0; g < G_; g++) g_w1[g] = w1[g];
        float s1 = bn_gamma[0] * rsqrtf(bn_var[0] + 1e-5f);
        float c1 = bn_beta[0] - bn_mean[0] * s1;
        g_aff[0] = s1;
        g_aff[1] = c1;
        g_aff[2] = w2[0];
        g_aff[3] = b2[0];

        // Detect degenerate homography: rot ~= I and trans_y ~= trans_z ~= 0
        // -> px = x + t0/depth, py = y. Tolerance absolute 1e-3 (rot entries
        // O(1), trans entries O(1e3) -> this is a tight structural test).
        bool fast = true;
        for (int s = 0; s < S_; s++) {
            for (int i = 0; i < 3; i++)
                for (int j = 0; j < 3; j++) {
                    float expect = (i == j) ? 1.0f : 0.0f;
                    if (fabsf(g_rot[s][i * 3 + j] - expect) > 1e-3f) fast = false;
                }
            if (fabsf(g_trans[s][1]) > 1e-3f) fast = false;
            if (fabsf(g_trans[s][2]) > 1e-3f) fast = false;
        }
        g_fast = fast ? 1 : 0;
        for (int s = 0; s < S_; s++) {
            float t0 = g_trans[s][0];
            for (int d = 0; d < D_; d++) {
                float shift = t0 / depths[d];
                float fs = floorf(shift);
                float wx = shift - fs;
                if (wx < SNAP_) { wx = 0.0f; }
                else if (wx > 1.0f - SNAP_) { wx = 0.0f; fs += 1.0f; }
                g_sdk[s][d] = (int)fs;
                g_sdw[s][d] = make_float2((1.0f - wx) * LOG2E_, wx * LOG2E_);
            }
        }
    }

    if (t < T1_) {
        int p = t % HW_;
        int sg = t / HW_;
        int s = sg / G_;
        int g = sg % G_;
        const float* b = srcF + (s * C_ + 4 * g) * HW_ + p;
        float4 v;
        v.x = b[0];
        v.y = b[HW_];
        v.z = b[2 * HW_];
        v.w = b[3 * HW_];
        g_src4[sg * HW_ + p] = v;
    } else if (t < T2_) {
        int u = t - T1_;
        int p = u % HW_;
        int g = u / HW_;
        const float* b = ref_feature + (g * 4) * HW_ + p;
        float e0 = __expf(b[0]);
        float e1 = __expf(b[HW_]);
        float e2 = __expf(b[2 * HW_]);
        float e3 = __expf(b[3 * HW_]);
        float is = __fdividef(1.0f, (e0 + e1) + (e2 + e3));
        float4 o;
        o.x = e0 * is;
        o.y = e1 * is;
        o.z = e2 * is;
        o.w = e3 * is;
        g_ref4[g * HW_ + p] = o;
    }
}

// ---------------------------------------------------------------------------
// Main fused kernel. Grid (W/32, H/4, D); block (32, 8).
// Fast path (g_fast): per-(s,d) tabulated shift/weights, 2-corner blend,
// per-thread geometry reduced to an add + clamp + validity select.
// Fallback: full per-thread projection geometry (general projections).
// ---------------------------------------------------------------------------
__global__ __launch_bounds__(256, 4) void fuse_kernel(const float* __restrict__ depths,
                                                      float* __restrict__ out) {
    __shared__ float s_lin[2][4][32][2];  // [half][row][lane][src]

    int tx = threadIdx.x;
    int ty = threadIdx.y;
    int row = ty & 3;
    int h = ty >> 2;                      // group half (warp-uniform)
    int x = blockIdx.x * 32 + tx;
    int y = blockIdx.y * 4 + row;
    int d = blockIdx.z;
    int p = y * W_ + x;

    int off0[S_], dxs[S_], dys[S_];
    u64 w00p[S_], w01p[S_], w10p[S_], w11p[S_];
    bool bottom = false;

    if (g_fast) {
#pragma unroll
        for (int s = 0; s < S_; s++) {
            int k = g_sdk[s][d];
            float2 wt = g_sdw[s][d];
            int xk = x + k;
            float w0 = ((unsigned)xk < W_) ? wt.x : 0.0f;
            float w1 = ((unsigned)(xk + 1) < W_) ? wt.y : 0.0f;
            int xi0 = min(max(xk, 0), W_ - 1);
            int xi1 = min(max(xk + 1, 0), W_ - 1);
            off0[s] = y * W_ + xi0;
            dxs[s] = xi1 - xi0;
            dys[s] = 0;
            w00p[s] = pk2(w0, w0);
            w01p[s] = pk2(w1, w1);
            w10p[s] = 0;
            w11p[s] = 0;
        }
    } else {
        float xf = (float)x, yf = (float)y;
        float depth = __ldg(depths + d);
        float wys[S_];
#pragma unroll
        for (int s = 0; s < S_; s++) {
            float X = fmaf(fmaf(g_rot[s][0], xf, fmaf(g_rot[s][1], yf, g_rot[s][2])), depth, g_trans[s][0]);
            float Y = fmaf(fmaf(g_rot[s][3], xf, fmaf(g_rot[s][4], yf, g_rot[s][5])), depth, g_trans[s][1]);
            float Z = fmaf(fmaf(g_rot[s][6], xf, fmaf(g_rot[s][7], yf, g_rot[s][8])), depth, g_trans[s][2]);
            float iz = __fdividef(1.0f, Z);
            float px = X * iz;
            float py = Y * iz;
            float x0f = floorf(px), y0f = floorf(py);
            float wx = px - x0f, wy = py - y0f;
            if (wx < SNAP_) { wx = 0.0f; }
            else if (wx > 1.0f - SNAP_) { wx = 0.0f; x0f += 1.0f; }
            if (wy < SNAP_) { wy = 0.0f; }
            else if (wy > 1.0f - SNAP_) { wy = 0.0f; y0f += 1.0f; }
            float vx0 = (x0f >= 0.0f && x0f <= (float)(W_ - 1)) ? LOG2E_ : 0.0f;
            float vx1 = (x0f + 1.0f >= 0.0f && x0f + 1.0f <= (float)(W_ - 1)) ? LOG2E_ : 0.0f;
            float vy0 = (y0f >= 0.0f && y0f <= (float)(H_ - 1)) ? 1.0f : 0.0f;
            float vy1 = (y0f + 1.0f >= 0.0f && y0f + 1.0f <= (float)(H_ - 1)) ? 1.0f : 0.0f;
            float wl = (1.0f - wx) * vx0, wr = wx * vx1;
            float wt = (1.0f - wy) * vy0, wb = wy * vy1;
            float w00 = wl * wt, w01 = wr * wt;
            float w10 = wl * wb, w11 = wr * wb;
            w00p[s] = pk2(w00, w00);
            w01p[s] = pk2(w01, w01);
            w10p[s] = pk2(w10, w10);
            w11p[s] = pk2(w11, w11);
            int xi0 = min(max((int)x0f, 0), W_ - 1);
            int yi0 = min(max((int)y0f, 0), H_ - 1);
            int xi1 = min(max((int)x0f + 1, 0), W_ - 1);
            int yi1 = min(max((int)y0f + 1, 0), H_ - 1);
            off0[s] = yi0 * W_ + xi0;
            dxs[s] = xi1 - xi0;
            dys[s] = (yi1 - yi0) * W_;
            wys[s] = wy;
        }
        bottom = (wys[0] + wys[1]) > 0.0f;
    }

    float v[S_][4];
    float lin0 = 0.0f, lin1 = 0.0f;
    int gbase = h * 4;

    const ulonglong2* sb0 = (const ulonglong2*)(g_src4 + (0 * G_ + gbase) * HW_ + off0[0]);
    const ulonglong2* sb1 = (const ulonglong2*)(g_src4 + (1 * G_ + gbase) * HW_ + off0[1]);
    const float4* rp = g_ref4 + gbase * HW_ + p;

    if (!bottom) {
#pragma unroll
        for (int j = 0; j < 4; j++) {
            float4 r = rp[j * HW_];
#pragma unroll
            for (int s = 0; s < S_; s++) {
                const ulonglong2* sb = (s == 0 ? sb0 : sb1) + j * HW_;
                ulonglong2 qa = sb[0];
                ulonglong2 qb = sb[dxs[s]];
                u64 a01 = fma2(w00p[s], qa.x, mul2(w01p[s], qb.x));
                u64 a23 = fma2(w00p[s], qa.y, mul2(w01p[s], qb.y));
                float a0, a1, a2, a3;
                upk2(a01, a0, a1);
                upk2(a23, a2, a3);
                float e0 = ex2f(a0), e1 = ex2f(a1);
                float e2 = ex2f(a2), e3 = ex2f(a3);
                float ssum = (e0 + e1) + (e2 + e3);
                float num = fmaf(e0, r.x, fmaf(e1, r.y, fmaf(e2, r.z, e3 * r.w)));
                float vv = __fdividef(num, ssum);
                v[s][j] = vv;
                if (s == 0) lin0 = fmaf(g_w1[gbase + j], vv, lin0);
                else        lin1 = fmaf(g_w1[gbase + j], vv, lin1);
            }
        }
    } else {
#pragma unroll
        for (int j = 0; j < 4; j++) {
            float4 r = rp[j * HW_];
#pragma unroll
            for (int s = 0; s < S_; s++) {
                const ulonglong2* sb = (s == 0 ? sb0 : sb1) + j * HW_;
                ulonglong2 qa = sb[0];
                ulonglong2 qb = sb[dxs[s]];
                ulonglong2 qc = sb[dys[s]];
                ulonglong2 qd = sb[dys[s] + dxs[s]];
                u64 a01 = fma2(w00p[s], qa.x, mul2(w01p[s], qb.x));
                u64 a23 = fma2(w00p[s], qa.y, mul2(w01p[s], qb.y));
                a01 = fma2(w10p[s], qc.x, fma2(w11p[s], qd.x, a01));
                a23 = fma2(w10p[s], qc.y, fma2(w11p[s], qd.y, a23));
                float a0, a1, a2, a3;
                upk2(a01, a0, a1);
                upk2(a23, a2, a3);
                float e0 = ex2f(a0), e1 = ex2f(a1);
                float e2 = ex2f(a2), e3 = ex2f(a3);
                float ssum = (e0 + e1) + (e2 + e3);
                float num = fmaf(e0, r.x, fmaf(e1, r.y, fmaf(e2, r.z, e3 * r.w)));
                float vv = __fdividef(num, ssum);
                v[s][j] = vv;
                if (s == 0) lin0 = fmaf(g_w1[gbase + j], vv, lin0);
                else        lin1 = fmaf(g_w1[gbase + j], vv, lin1);
            }
        }
    }

    // Exchange partial lin sums across the two group-halves
    s_lin[h][row][tx][0] = lin0;
    s_lin[h][row][tx][1] = lin1;
    __syncthreads();
    float L0 = s_lin[0][row][tx][0] + s_lin[1][row][tx][0];
    float L1 = s_lin[0][row][tx][1] + s_lin[1][row][tx][1];

    float s1 = g_aff[0], c1 = g_aff[1], w2c = g_aff[2], b2c = g_aff[3];
    float bn0 = fmaf(L0, s1, c1);
    float bn1 = fmaf(L1, s1, c1);
    float ac0 = fmaf(fmaxf(bn0, 0.0f), w2c, b2c);
    float ac1 = fmaf(fmaxf(bn1, 0.0f), w2c, b2c);
    float wgt0 = __fdividef(1.0f, 1.0f + __expf(-ac0));
    float wgt1 = __fdividef(1.0f, 1.0f + __expf(-ac1));
    float iw = __fdividef(1.0f, wgt0 + wgt1);

    float* op = out + (gbase * D_ + d) * HW_ + p;
#pragma unroll
    for (int j = 0; j < 4; j++) {
        op[j * (D_ * HW_)] = (wgt0 * v[0][j] + wgt1 * v[1][j]) * iw;
    }
}

// ---------------------------------------------------------------------------
// Launch
// ---------------------------------------------------------------------------
extern "C" void kernel_launch(void* const* d_in, const int* in_sizes, int n_in,
                              void* d_out, int out_size) {
    const float* ref_feature = (const float*)d_in[0];
    const float* src_features = (const float*)d_in[1];
    const float* ref_proj = (const float*)d_in[2];
    const float* src_projs = (const float*)d_in[3];
    const float* depth_hypos = (const float*)d_in[4];
    const float* w1 = (const float*)d_in[5];
    const float* bn_gamma = (const float*)d_in[6];
    const float* bn_beta = (const float*)d_in[7];
    const float* bn_mean = (const float*)d_in[8];
    const float* bn_var = (const float*)d_in[9];
    const float* w2 = (const float*)d_in[10];
    const float* b2 = (const float*)d_in[11];
    float* out = (float*)d_out;

    prep_all_kernel<<<(T2_ + 255) / 256, 256>>>(
        ref_feature, src_features, ref_proj, src_projs, depth_hypos, w1,
        bn_gamma, bn_beta, bn_mean, bn_var, w2, b2);

    dim3 grid(W_ / 32, H_ / 4, D_);
    dim3 block(32, 8);
    fuse_kernel<<<grid, block>>>(depth_hypos, out);
}

// round 8
// speedup vs baseline: 1.1701x; 1.1590x over previous
#include <cuda_runtime.h>
#include <math.h>

// Problem shape (fixed by the dataset)
#define W_ 160
#define H_ 128
#define C_ 32
#define G_ 8
#define D_ 48
#define S_ 2
#define HW_ (H_ * W_)

#define SNAP_ 3e-5f
#define LOG2E_ 1.44269504088896340736f

// Scratch (no cudaMalloc allowed)
__device__ float4 g_ref4[G_ * HW_];          // ref softmax, channel-packed
__device__ float4 g_src4[S_ * G_ * HW_];     // src features, channel-packed
__device__ float g_rot[S_][9];
__device__ float g_trans[S_][3];
__device__ float g_w1[G_];
__device__ float g_aff[4];  // s1, c1, w2, b2
// Fast-geometry tables (valid when g_fast != 0): per (s,d) integer shift and
// snap-folded bilinear weights (log2e included).
__device__ int    g_fast;
__device__ int    g_sdk[S_][D_];
__device__ float2 g_sdw[S_][D_];

typedef unsigned long long u64;

__device__ __forceinline__ float ex2f(float x) {
    float y; asm("ex2.approx.f32 %0, %1;" : "=f"(y) : "f"(x)); return y;
}
__device__ __forceinline__ u64 pk2(float a, float b) {
    u64 r; asm("mov.b64 %0, {%1, %2};" : "=l"(r) : "f"(a), "f"(b)); return r;
}
__device__ __forceinline__ void upk2(u64 v, float& a, float& b) {
    asm("mov.b64 {%0, %1}, %2;" : "=f"(a), "=f"(b) : "l"(v));
}
__device__ __forceinline__ u64 fma2(u64 a, u64 b, u64 c) {
    u64 r; asm("fma.rn.f32x2 %0, %1, %2, %3;" : "=l"(r) : "l"(a), "l"(b), "l"(c)); return r;
}
__device__ __forceinline__ u64 mul2(u64 a, u64 b) {
    u64 r; asm("mul.rn.f32x2 %0, %1, %2;" : "=l"(r) : "l"(a), "l"(b)); return r;
}

// ---------------------------------------------------------------------------
// Prep (single fused kernel):
//   block 0 / thread 0: params + fast-detect (serial, small)
//   block 0 / threads 0..S*D-1 (after __syncthreads): geometry table, parallel
//   all threads: src transpose + ref softmax
// ---------------------------------------------------------------------------
#define T1_ (S_ * G_ * HW_)
#define T2_ (T1_ + G_ * HW_)

__global__ __launch_bounds__(256) void prep_all_kernel(
    const float* __restrict__ ref_feature,
    const float* __restrict__ srcF,
    const float* __restrict__ ref_proj,
    const float* __restrict__ src_projs,
    const float* __restrict__ depths,
    const float* __restrict__ w1,
    const float* __restrict__ bn_gamma,
    const float* __restrict__ bn_beta,
    const float* __restrict__ bn_mean,
    const float* __restrict__ bn_var,
    const float* __restrict__ w2,
    const float* __restrict__ b2) {
    int t = blockIdx.x * blockDim.x + threadIdx.x;

    if (blockIdx.x == 0) {
        if (threadIdx.x == 0) {
            float a[4][8];
            for (int i = 0; i < 4; i++)
                for (int j = 0; j < 4; j++) {
                    a[i][j] = ref_proj[i * 4 + j];
                    a[i][4 + j] = (i == j) ? 1.0f : 0.0f;
                }
            for (int col = 0; col < 4; col++) {
                int piv = col;
                float best = fabsf(a[col][col]);
                for (int r = col + 1; r < 4; r++) {
                    float v = fabsf(a[r][col]);
                    if (v > best) { best = v; piv = r; }
                }
                if (piv != col)
                    for (int j = 0; j < 8; j++) {
                        float tmp = a[col][j]; a[col][j] = a[piv][j]; a[piv][j] = tmp;
                    }
                float inv = 1.0f / a[col][col];
                for (int j = 0; j < 8; j++) a[col][j] *= inv;
                for (int r = 0; r < 4; r++) {
                    if (r == col) continue;
                    float f = a[r][col];
                    for (int j = 0; j < 8; j++) a[r][j] -= f * a[col][j];
                }
            }
            for (int s = 0; s < S_; s++) {
                const float* sp = src_projs + s * 16;
                for (int i = 0; i < 3; i++) {
                    float pr[4];
                    for (int j = 0; j < 4; j++) {
                        float acc = 0.0f;
                        for (int k = 0; k < 4; k++)
                            acc += sp[i * 4 + k] * a[k][4 + j];
                        pr[j] = acc;
                    }
                    g_rot[s][i * 3 + 0] = pr[0];
                    g_rot[s][i * 3 + 1] = pr[1];
                    g_rot[s][i * 3 + 2] = pr[2];
                    g_trans[s][i] = pr[3];
                }
            }
            for (int g = 0; g < G_; g++) g_w1[g] = w1[g];
            float s1 = bn_gamma[0] * rsqrtf(bn_var[0] + 1e-5f);
            float c1 = bn_beta[0] - bn_mean[0] * s1;
            g_aff[0] = s1;
            g_aff[1] = c1;
            g_aff[2] = w2[0];
            g_aff[3] = b2[0];

            // Detect degenerate homography: rot ~= I, trans_y ~= trans_z ~= 0
            // -> px = x + t0/depth, py = y.
            bool fast = true;
            for (int s = 0; s < S_; s++) {
                for (int i = 0; i < 3; i++)
                    for (int j = 0; j < 3; j++) {
                        float expect = (i == j) ? 1.0f : 0.0f;
                        if (fabsf(g_rot[s][i * 3 + j] - expect) > 1e-3f) fast = false;
                    }
                if (fabsf(g_trans[s][1]) > 1e-3f) fast = false;
                if (fabsf(g_trans[s][2]) > 1e-3f) fast = false;
            }
            g_fast = fast ? 1 : 0;
        }
        __syncthreads();  // block-uniform: all threads of block 0 participate
        if (threadIdx.x < S_ * D_) {
            int s = threadIdx.x / D_;
            int d = threadIdx.x % D_;
            float shift = __fdividef(g_trans[s][0], depths[d]);
            float fs = floorf(shift);
            float wx = shift - fs;
            if (wx < SNAP_) { wx = 0.0f; }
            else if (wx > 1.0f - SNAP_) { wx = 0.0f; fs += 1.0f; }
            g_sdk[s][d] = (int)fs;
            g_sdw[s][d] = make_float2((1.0f - wx) * LOG2E_, wx * LOG2E_);
        }
    }

    if (t < T1_) {
        int p = t % HW_;
        int sg = t / HW_;
        int s = sg / G_;
        int g = sg % G_;
        const float* b = srcF + (s * C_ + 4 * g) * HW_ + p;
        float4 v;
        v.x = b[0];
        v.y = b[HW_];
        v.z = b[2 * HW_];
        v.w = b[3 * HW_];
        g_src4[sg * HW_ + p] = v;
    } else if (t < T2_) {
        int u = t - T1_;
        int p = u % HW_;
        int g = u / HW_;
        const float* b = ref_feature + (g * 4) * HW_ + p;
        float e0 = __expf(b[0]);
        float e1 = __expf(b[HW_]);
        float e2 = __expf(b[2 * HW_]);
        float e3 = __expf(b[3 * HW_]);
        float is = __fdividef(1.0f, (e0 + e1) + (e2 + e3));
        float4 o;
        o.x = e0 * is;
        o.y = e1 * is;
        o.z = e2 * is;
        o.w = e3 * is;
        g_ref4[g * HW_ + p] = o;
    }
}

// ---------------------------------------------------------------------------
// Main fused kernel. Grid (W/32, H/4, D); block (32, 8).
// Fast path (g_fast): per-(s,d) tabulated shift/weights, 2-corner blend.
// Fallback: full per-thread projection geometry (general projections).
// ---------------------------------------------------------------------------
__global__ __launch_bounds__(256, 4) void fuse_kernel(const float* __restrict__ depths,
                                                      float* __restrict__ out) {
    __shared__ float s_lin[2][4][32][2];  // [half][row][lane][src]

    int tx = threadIdx.x;
    int ty = threadIdx.y;
    int row = ty & 3;
    int h = ty >> 2;                      // group half (warp-uniform)
    int x = blockIdx.x * 32 + tx;
    int y = blockIdx.y * 4 + row;
    int d = blockIdx.z;
    int p = y * W_ + x;

    int off0[S_], dxs[S_], dys[S_];
    u64 w00p[S_], w01p[S_], w10p[S_], w11p[S_];
    bool bottom = false;

    if (g_fast) {
#pragma unroll
        for (int s = 0; s < S_; s++) {
            int k = g_sdk[s][d];
            float2 wt = g_sdw[s][d];
            int xk = x + k;
            float w0 = ((unsigned)xk < W_) ? wt.x : 0.0f;
            float w1 = ((unsigned)(xk + 1) < W_) ? wt.y : 0.0f;
            int xi0 = min(max(xk, 0), W_ - 1);
            int xi1 = min(max(xk + 1, 0), W_ - 1);
            off0[s] = y * W_ + xi0;
            dxs[s] = xi1 - xi0;
            dys[s] = 0;
            w00p[s] = pk2(w0, w0);
            w01p[s] = pk2(w1, w1);
            w10p[s] = 0;
            w11p[s] = 0;
        }
    } else {
        float xf = (float)x, yf = (float)y;
        float depth = __ldg(depths + d);
        float wys[S_];
#pragma unroll
        for (int s = 0; s < S_; s++) {
            float X = fmaf(fmaf(g_rot[s][0], xf, fmaf(g_rot[s][1], yf, g_rot[s][2])), depth, g_trans[s][0]);
            float Y = fmaf(fmaf(g_rot[s][3], xf, fmaf(g_rot[s][4], yf, g_rot[s][5])), depth, g_trans[s][1]);
            float Z = fmaf(fmaf(g_rot[s][6], xf, fmaf(g_rot[s][7], yf, g_rot[s][8])), depth, g_trans[s][2]);
            float iz = __fdividef(1.0f, Z);
            float px = X * iz;
            float py = Y * iz;
            float x0f = floorf(px), y0f = floorf(py);
            float wx = px - x0f, wy = py - y0f;
            if (wx < SNAP_) { wx = 0.0f; }
            else if (wx > 1.0f - SNAP_) { wx = 0.0f; x0f += 1.0f; }
            if (wy < SNAP_) { wy = 0.0f; }
            else if (wy > 1.0f - SNAP_) { wy = 0.0f; y0f += 1.0f; }
            float vx0 = (x0f >= 0.0f && x0f <= (float)(W_ - 1)) ? LOG2E_ : 0.0f;
            float vx1 = (x0f + 1.0f >= 0.0f && x0f + 1.0f <= (float)(W_ - 1)) ? LOG2E_ : 0.0f;
            float vy0 = (y0f >= 0.0f && y0f <= (float)(H_ - 1)) ? 1.0f : 0.0f;
            float vy1 = (y0f + 1.0f >= 0.0f && y0f + 1.0f <= (float)(H_ - 1)) ? 1.0f : 0.0f;
            float wl = (1.0f - wx) * vx0, wr = wx * vx1;
            float wt = (1.0f - wy) * vy0, wb = wy * vy1;
            float w00 = wl * wt, w01 = wr * wt;
            float w10 = wl * wb, w11 = wr * wb;
            w00p[s] = pk2(w00, w00);
            w01p[s] = pk2(w01, w01);
            w10p[s] = pk2(w10, w10);
            w11p[s] = pk2(w11, w11);
            int xi0 = min(max((int)x0f, 0), W_ - 1);
            int yi0 = min(max((int)y0f, 0), H_ - 1);
            int xi1 = min(max((int)x0f + 1, 0), W_ - 1);
            int yi1 = min(max((int)y0f + 1, 0), H_ - 1);
            off0[s] = yi0 * W_ + xi0;
            dxs[s] = xi1 - xi0;
            dys[s] = (yi1 - yi0) * W_;
            wys[s] = wy;
        }
        bottom = (wys[0] + wys[1]) > 0.0f;
    }

    float v[S_][4];
    float lin0 = 0.0f, lin1 = 0.0f;
    int gbase = h * 4;

    const ulonglong2* sb0 = (const ulonglong2*)(g_src4 + (0 * G_ + gbase) * HW_ + off0[0]);
    const ulonglong2* sb1 = (const ulonglong2*)(g_src4 + (1 * G_ + gbase) * HW_ + off0[1]);
    const float4* rp = g_ref4 + gbase * HW_ + p;

    if (!bottom) {
#pragma unroll
        for (int j = 0; j < 4; j++) {
            float4 r = rp[j * HW_];
#pragma unroll
            for (int s = 0; s < S_; s++) {
                const ulonglong2* sb = (s == 0 ? sb0 : sb1) + j * HW_;
                ulonglong2 qa = sb[0];
                ulonglong2 qb = sb[dxs[s]];
                u64 a01 = fma2(w00p[s], qa.x, mul2(w01p[s], qb.x));
                u64 a23 = fma2(w00p[s], qa.y, mul2(w01p[s], qb.y));
                float a0, a1, a2, a3;
                upk2(a01, a0, a1);
                upk2(a23, a2, a3);
                float e0 = ex2f(a0), e1 = ex2f(a1);
                float e2 = ex2f(a2), e3 = ex2f(a3);
                float ssum = (e0 + e1) + (e2 + e3);
                float num = fmaf(e0, r.x, fmaf(e1, r.y, fmaf(e2, r.z, e3 * r.w)));
                float vv = __fdividef(num, ssum);
                v[s][j] = vv;
                if (s == 0) lin0 = fmaf(g_w1[gbase + j], vv, lin0);
                else        lin1 = fmaf(g_w1[gbase + j], vv, lin1);
            }
        }
    } else {
#pragma unroll
        for (int j = 0; j < 4; j++) {
            float4 r = rp[j * HW_];
#pragma unroll
            for (int s = 0; s < S_; s++) {
                const ulonglong2* sb = (s == 0 ? sb0 : sb1) + j * HW_;
                ulonglong2 qa = sb[0];
                ulonglong2 qb = sb[dxs[s]];
                ulonglong2 qc = sb[dys[s]];
                ulonglong2 qd = sb[dys[s] + dxs[s]];
                u64 a01 = fma2(w00p[s], qa.x, mul2(w01p[s], qb.x));
                u64 a23 = fma2(w00p[s], qa.y, mul2(w01p[s], qb.y));
                a01 = fma2(w10p[s], qc.x, fma2(w11p[s], qd.x, a01));
                a23 = fma2(w10p[s], qc.y, fma2(w11p[s], qd.y, a23));
                float a0, a1, a2, a3;
                upk2(a01, a0, a1);
                upk2(a23, a2, a3);
                float e0 = ex2f(a0), e1 = ex2f(a1);
                float e2 = ex2f(a2), e3 = ex2f(a3);
                float ssum = (e0 + e1) + (e2 + e3);
                float num = fmaf(e0, r.x, fmaf(e1, r.y, fmaf(e2, r.z, e3 * r.w)));
                float vv = __fdividef(num, ssum);
                v[s][j] = vv;
                if (s == 0) lin0 = fmaf(g_w1[gbase + j], vv, lin0);
                else        lin1 = fmaf(g_w1[gbase + j], vv, lin1);
            }
        }
    }

    // Exchange partial lin sums across the two group-halves
    s_lin[h][row][tx][0] = lin0;
    s_lin[h][row][tx][1] = lin1;
    __syncthreads();
    float L0 = s_lin[0][row][tx][0] + s_lin[1][row][tx][0];
    float L1 = s_lin[0][row][tx][1] + s_lin[1][row][tx][1];

    float s1 = g_aff[0], c1 = g_aff[1], w2c = g_aff[2], b2c = g_aff[3];
    float bn0 = fmaf(L0, s1, c1);
    float bn1 = fmaf(L1, s1, c1);
    float ac0 = fmaf(fmaxf(bn0, 0.0f), w2c, b2c);
    float ac1 = fmaf(fmaxf(bn1, 0.0f), w2c, b2c);
    float wgt0 = __fdividef(1.0f, 1.0f + __expf(-ac0));
    float wgt1 = __fdividef(1.0f, 1.0f + __expf(-ac1));
    float iw = __fdividef(1.0f, wgt0 + wgt1);

    float* op = out + (gbase * D_ + d) * HW_ + p;
#pragma unroll
    for (int j = 0; j < 4; j++) {
        op[j * (D_ * HW_)] = (wgt0 * v[0][j] + wgt1 * v[1][j]) * iw;
    }
}

// ---------------------------------------------------------------------------
// Launch
// ---------------------------------------------------------------------------
extern "C" void kernel_launch(void* const* d_in, const int* in_sizes, int n_in,
                              void* d_out, int out_size) {
    const float* ref_feature = (const float*)d_in[0];
    const float* src_features = (const float*)d_in[1];
    const float* ref_proj = (const float*)d_in[2];
    const float* src_projs = (const float*)d_in[3];
    const float* depth_hypos = (const float*)d_in[4];
    const float* w1 = (const float*)d_in[5];
    const float* bn_gamma = (const float*)d_in[6];
    const float* bn_beta = (const float*)d_in[7];
    const float* bn_mean = (const float*)d_in[8];
    const float* bn_var = (const float*)d_in[9];
    const float* w2 = (const float*)d_in[10];
    const float* b2 = (const float*)d_in[11];
    float* out = (float*)d_out;

    prep_all_kernel<<<(T2_ + 255) / 256, 256>>>(
        ref_feature, src_features, ref_proj, src_projs, depth_hypos, w1,
        bn_gamma, bn_beta, bn_mean, bn_var, w2, b2);

    dim3 grid(W_ / 32, H_ / 4, D_);
    dim3 block(32, 8);
    fuse_kernel<<<grid, block>>>(depth_hypos, out);
}

// round 10
// speedup vs baseline: 1.1959x; 1.0220x over previous
#include <cuda_runtime.h>
#include <math.h>

// Problem shape (fixed by the dataset)
#define W_ 160
#define H_ 128
#define C_ 32
#define G_ 8
#define D_ 48
#define S_ 2
#define HW_ (H_ * W_)
#define DBLK_ 4
#define NDB_ (D_ / DBLK_)

#define SNAP_ 3e-5f
#define LOG2E_ 1.44269504088896340736f

// Scratch (no cudaMalloc allowed)
__device__ float4 g_ref4[G_ * HW_];          // ref softmax, channel-packed
__device__ float4 g_src4[S_ * G_ * HW_];     // src features, channel-packed
__device__ float g_rot[S_][9];
__device__ float g_trans[S_][3];
__device__ float g_w1[G_];
__device__ float g_aff[4];  // s1, c1, w2, b2
// Fast-geometry tables (valid when g_fast != 0): per (s, depth-block) base
// integer shift and per (s,d) 3-slot aligned bilinear weights (log2e folded).
__device__ int    g_fast;
__device__ int    g_kb[S_][NDB_];
__device__ float4 g_w3[S_][D_];

typedef unsigned long long u64;

__device__ __forceinline__ float ex2f(float x) {
    float y; asm("ex2.approx.f32 %0, %1;" : "=f"(y) : "f"(x)); return y;
}
__device__ __forceinline__ u64 pk2(float a, float b) {
    u64 r; asm("mov.b64 %0, {%1, %2};" : "=l"(r) : "f"(a), "f"(b)); return r;
}
__device__ __forceinline__ void upk2(u64 v, float& a, float& b) {
    asm("mov.b64 {%0, %1}, %2;" : "=f"(a), "=f"(b) : "l"(v));
}
__device__ __forceinline__ u64 fma2(u64 a, u64 b, u64 c) {
    u64 r; asm("fma.rn.f32x2 %0, %1, %2, %3;" : "=l"(r) : "l"(a), "l"(b), "l"(c)); return r;
}
__device__ __forceinline__ u64 mul2(u64 a, u64 b) {
    u64 r; asm("mul.rn.f32x2 %0, %1, %2;" : "=l"(r) : "l"(a), "l"(b)); return r;
}

// ---------------------------------------------------------------------------
// Prep (single fused kernel):
//   block 0 / thread 0: params + fast-detect; then threads 0..S*D-1 build the
//   depth-block weight tables (parallel, __fdividef).
//   all threads: src transpose + ref softmax
// ---------------------------------------------------------------------------
#define T1_ (S_ * G_ * HW_)
#define T2_ (T1_ + G_ * HW_)

__global__ __launch_bounds__(256) void prep_all_kernel(
    const float* __restrict__ ref_feature,
    const float* __restrict__ srcF,
    const float* __restrict__ ref_proj,
    const float* __restrict__ src_projs,
    const float* __restrict__ depths,
    const float* __restrict__ w1,
    const float* __restrict__ bn_gamma,
    const float* __restrict__ bn_beta,
    const float* __restrict__ bn_mean,
    const float* __restrict__ bn_var,
    const float* __restrict__ w2,
    const float* __restrict__ b2) {
    int t = blockIdx.x * blockDim.x + threadIdx.x;

    if (blockIdx.x == 0) {
        if (threadIdx.x == 0) {
            float a[4][8];
            for (int i = 0; i < 4; i++)
                for (int j = 0; j < 4; j++) {
                    a[i][j] = ref_proj[i * 4 + j];
                    a[i][4 + j] = (i == j) ? 1.0f : 0.0f;
                }
            for (int col = 0; col < 4; col++) {
                int piv = col;
                float best = fabsf(a[col][col]);
                for (int r = col + 1; r < 4; r++) {
                    float v = fabsf(a[r][col]);
                    if (v > best) { best = v; piv = r; }
                }
                if (piv != col)
                    for (int j = 0; j < 8; j++) {
                        float tmp = a[col][j]; a[col][j] = a[piv][j]; a[piv][j] = tmp;
                    }
                float inv = 1.0f / a[col][col];
                for (int j = 0; j < 8; j++) a[col][j] *= inv;
                for (int r = 0; r < 4; r++) {
                    if (r == col) continue;
                    float f = a[r][col];
                    for (int j = 0; j < 8; j++) a[r][j] -= f * a[col][j];
                }
            }
            for (int s = 0; s < S_; s++) {
                const float* sp = src_projs + s * 16;
                for (int i = 0; i < 3; i++) {
                    float pr[4];
                    for (int j = 0; j < 4; j++) {
                        float acc = 0.0f;
                        for (int k = 0; k < 4; k++)
                            acc += sp[i * 4 + k] * a[k][4 + j];
                        pr[j] = acc;
                    }
                    g_rot[s][i * 3 + 0] = pr[0];
                    g_rot[s][i * 3 + 1] = pr[1];
                    g_rot[s][i * 3 + 2] = pr[2];
                    g_trans[s][i] = pr[3];
                }
            }
            for (int g = 0; g < G_; g++) g_w1[g] = w1[g];
            float s1 = bn_gamma[0] * rsqrtf(bn_var[0] + 1e-5f);
            float c1 = bn_beta[0] - bn_mean[0] * s1;
            g_aff[0] = s1;
            g_aff[1] = c1;
            g_aff[2] = w2[0];
            g_aff[3] = b2[0];

            // Detect degenerate homography: rot ~= I, trans_y ~= trans_z ~= 0
            bool fast = true;
            for (int s = 0; s < S_; s++) {
                for (int i = 0; i < 3; i++)
                    for (int j = 0; j < 3; j++) {
                        float expect = (i == j) ? 1.0f : 0.0f;
                        if (fabsf(g_rot[s][i * 3 + j] - expect) > 1e-3f) fast = false;
                    }
                if (fabsf(g_trans[s][1]) > 1e-3f) fast = false;
                if (fabsf(g_trans[s][2]) > 1e-3f) fast = false;
            }
            g_fast = fast ? 1 : 0;
        }
        __syncthreads();  // block-uniform
        if (threadIdx.x < S_ * D_) {
            int s = threadIdx.x / D_;
            int d = threadIdx.x % D_;
            int dblk = d / DBLK_;
            float t0 = g_trans[s][0];
            int kmin = 0x7fffffff, kd = 0;
            float wxd = 0.0f;
            for (int dl = 0; dl < DBLK_; dl++) {
                int dd = dblk * DBLK_ + dl;
                float shift = __fdividef(t0, depths[dd]);
                float fs = floorf(shift);
                float wx = shift - fs;
                if (wx < SNAP_) { wx = 0.0f; }
                else if (wx > 1.0f - SNAP_) { wx = 0.0f; fs += 1.0f; }
                int k = (int)fs;
                kmin = min(kmin, k);
                if (dd == d) { kd = k; wxd = wx; }
            }
            if ((d & (DBLK_ - 1)) == 0) g_kb[s][dblk] = kmin;
            int delta = kd - kmin;
            if (delta > 1) atomicExch(&g_fast, 0);  // fast tables invalid
            float wlo = (1.0f - wxd) * LOG2E_;
            float whi = wxd * LOG2E_;
            float4 w3 = make_float4(0.0f, 0.0f, 0.0f, 0.0f);
            if (delta == 0) { w3.x = wlo; w3.y = whi; }
            else            { w3.y = wlo; w3.z = whi; }
            g_w3[s][d] = w3;
        }
    }

    if (t < T1_) {
        int p = t % HW_;
        int sg = t / HW_;
        int s = sg / G_;
        int g = sg % G_;
        const float* b = srcF + (s * C_ + 4 * g) * HW_ + p;
        float4 v;
        v.x = b[0];
        v.y = b[HW_];
        v.z = b[2 * HW_];
        v.w = b[3 * HW_];
        g_src4[sg * HW_ + p] = v;
    } else if (t < T2_) {
        int u = t - T1_;
        int p = u % HW_;
        int g = u / HW_;
        const float* b = ref_feature + (g * 4) * HW_ + p;
        float e0 = __expf(b[0]);
        float e1 = __expf(b[HW_]);
        float e2 = __expf(b[2 * HW_]);
        float e3 = __expf(b[3 * HW_]);
        float is = __fdividef(1.0f, (e0 + e1) + (e2 + e3));
        float4 o;
        o.x = e0 * is;
        o.y = e1 * is;
        o.z = e2 * is;
        o.w = e3 * is;
        g_ref4[g * HW_ + p] = o;
    }
}

// ---------------------------------------------------------------------------
// Main fused kernel. Grid (W/32, H, D/4); block (32, 8).
// Thread = (x=tx, y=blockIdx.y, group g=ty, 4 consecutive depths).
// Fast path: 3 contiguous src taps per source loaded ONCE serve all 4 depths
// via per-(s,d) aligned 3-slot weights; ref softmax vector loaded once.
// Sigmoid weight computed once per (x,d) by 4 reducer warps via smem.
// Fallback: full per-thread geometry per depth (general projections).
// ---------------------------------------------------------------------------
__global__ __launch_bounds__(256, 3) void fuse_kernel(const float* __restrict__ depths,
                                                      float* __restrict__ out) {
    __shared__ float s_lin[DBLK_][2][G_][32];  // [dl][src][g][tx]
    __shared__ float s_w[DBLK_][2][32];        // [dl][src][tx] = wgt*iw

    int tx = threadIdx.x;
    int g = threadIdx.y;                  // group (warp-uniform)
    int x = blockIdx.x * 32 + tx;
    int y = blockIdx.y;
    int dblk = blockIdx.z;
    int d0 = dblk * DBLK_;
    int p = y * W_ + x;

    float v0[DBLK_], v1[DBLK_];

    if (g_fast) {
        // Load 3 taps per source once (zeroed when out of range)
        ulonglong2 q[S_][3];
#pragma unroll
        for (int s = 0; s < S_; s++) {
            int kb = g_kb[s][dblk];
            const ulonglong2* sp = (const ulonglong2*)(g_src4 + (s * G_ + g) * HW_ + y * W_);
#pragma unroll
            for (int j = 0; j < 3; j++) {
                int xc = x + kb + j;
                bool valid = ((unsigned)xc < W_);
                int xi = min(max(xc, 0), W_ - 1);
                ulonglong2 qq = sp[xi];
                q[s][j].x = valid ? qq.x : 0ull;
                q[s][j].y = valid ? qq.y : 0ull;
            }
        }
        float4 r = g_ref4[g * HW_ + p];

#pragma unroll
        for (int dl = 0; dl < DBLK_; dl++) {
            float vv[2];
#pragma unroll
            for (int s = 0; s < S_; s++) {
                float4 w3 = g_w3[s][d0 + dl];
                u64 wa = pk2(w3.x, w3.x);
                u64 wb = pk2(w3.y, w3.y);
                u64 wc = pk2(w3.z, w3.z);
                u64 a01 = fma2(wa, q[s][0].x, fma2(wb, q[s][1].x, mul2(wc, q[s][2].x)));
                u64 a23 = fma2(wa, q[s][0].y, fma2(wb, q[s][1].y, mul2(wc, q[s][2].y)));
                float a0, a1, a2, a3;
                upk2(a01, a0, a1);
                upk2(a23, a2, a3);
                float e0 = ex2f(a0), e1 = ex2f(a1);
                float e2 = ex2f(a2), e3 = ex2f(a3);
                float ss = (e0 + e1) + (e2 + e3);
                float num = fmaf(e0, r.x, fmaf(e1, r.y, fmaf(e2, r.z, e3 * r.w)));
                vv[s] = __fdividef(num, ss);
            }
            v0[dl] = vv[0];
            v1[dl] = vv[1];
        }
    } else {
        // General path: full geometry per depth (correctness fallback)
        const float4* sb0 = g_src4 + (0 * G_ + g) * HW_;
        const float4* sb1 = g_src4 + (1 * G_ + g) * HW_;
        float4 r = g_ref4[g * HW_ + p];
        float xf = (float)x, yf = (float)y;
#pragma unroll
        for (int dl = 0; dl < DBLK_; dl++) {
            float depth = __ldg(depths + d0 + dl);
            float vv[2];
#pragma unroll
            for (int s = 0; s < S_; s++) {
                float X = fmaf(fmaf(g_rot[s][0], xf, fmaf(g_rot[s][1], yf, g_rot[s][2])), depth, g_trans[s][0]);
                float Y = fmaf(fmaf(g_rot[s][3], xf, fmaf(g_rot[s][4], yf, g_rot[s][5])), depth, g_trans[s][1]);
                float Z = fmaf(fmaf(g_rot[s][6], xf, fmaf(g_rot[s][7], yf, g_rot[s][8])), depth, g_trans[s][2]);
                float iz = __fdividef(1.0f, Z);
                float px = X * iz;
                float py = Y * iz;
                float x0f = floorf(px), y0f = floorf(py);
                float wx = px - x0f, wy = py - y0f;
                if (wx < SNAP_) { wx = 0.0f; }
                else if (wx > 1.0f - SNAP_) { wx = 0.0f; x0f += 1.0f; }
                if (wy < SNAP_) { wy = 0.0f; }
                else if (wy > 1.0f - SNAP_) { wy = 0.0f; y0f += 1.0f; }
                float vx0 = (x0f >= 0.0f && x0f <= (float)(W_ - 1)) ? LOG2E_ : 0.0f;
                float vx1 = (x0f + 1.0f >= 0.0f && x0f + 1.0f <= (float)(W_ - 1)) ? LOG2E_ : 0.0f;
                float vy0 = (y0f >= 0.0f && y0f <= (float)(H_ - 1)) ? 1.0f : 0.0f;
                float vy1 = (y0f + 1.0f >= 0.0f && y0f + 1.0f <= (float)(H_ - 1)) ? 1.0f : 0.0f;
                float wl = (1.0f - wx) * vx0, wr = wx * vx1;
                float wt = (1.0f - wy) * vy0, wb = wy * vy1;
                int xi0 = min(max((int)x0f, 0), W_ - 1);
                int yi0 = min(max((int)y0f, 0), H_ - 1);
                int xi1 = min(max((int)x0f + 1, 0), W_ - 1);
                int yi1 = min(max((int)y0f + 1, 0), H_ - 1);
                const float4* sb = (s == 0) ? sb0 : sb1;
                float4 qa = sb[yi0 * W_ + xi0];
                float4 qb = sb[yi0 * W_ + xi1];
                float4 qc = sb[yi1 * W_ + xi0];
                float4 qd = sb[yi1 * W_ + xi1];
                float w00 = wl * wt, w01 = wr * wt, w10 = wl * wb, w11 = wr * wb;
                float a0 = fmaf(w00, qa.x, fmaf(w01, qb.x, fmaf(w10, qc.x, w11 * qd.x)));
                float a1 = fmaf(w00, qa.y, fmaf(w01, qb.y, fmaf(w10, qc.y, w11 * qd.y)));
                float a2 = fmaf(w00, qa.z, fmaf(w01, qb.z, fmaf(w10, qc.z, w11 * qd.z)));
                float a3 = fmaf(w00, qa.w, fmaf(w01, qb.w, fmaf(w10, qc.w, w11 * qd.w)));
                float e0 = ex2f(a0), e1 = ex2f(a1);
                float e2 = ex2f(a2), e3 = ex2f(a3);
                float ss = (e0 + e1) + (e2 + e3);
                float num = fmaf(e0, r.x, fmaf(e1, r.y, fmaf(e2, r.z, e3 * r.w)));
                vv[s] = __fdividef(num, ss);
            }
            v0[dl] = vv[0];
            v1[dl] = vv[1];
        }
    }

    // Stage per-group lin contributions; 4 reducer warps compute sigmoid
    // weights once per (x, d); all threads then scale and store.
    float w1g = g_w1[g];
#pragma unroll
    for (int dl = 0; dl < DBLK_; dl++) {
        s_lin[dl][0][g][tx] = w1g * v0[dl];
        s_lin[dl][1][g][tx] = w1g * v1[dl];
    }
    __syncthreads();
    if (g < DBLK_) {
        int dl = g;
        float L0 = 0.0f, L1 = 0.0f;
#pragma unroll
        for (int gg = 0; gg < G_; gg++) {
            L0 += s_lin[dl][0][gg][tx];
            L1 += s_lin[dl][1][gg][tx];
        }
        float s1 = g_aff[0], c1 = g_aff[1], w2c = g_aff[2], b2c = g_aff[3];
        float bn0 = fmaf(L0, s1, c1);
        float bn1 = fmaf(L1, s1, c1);
        float ac0 = fmaf(fmaxf(bn0, 0.0f), w2c, b2c);
        float ac1 = fmaf(fmaxf(bn1, 0.0f), w2c, b2c);
        float wgt0 = __fdividef(1.0f, 1.0f + __expf(-ac0));
        float wgt1 = __fdividef(1.0f, 1.0f + __expf(-ac1));
        float iw = __fdividef(1.0f, wgt0 + wgt1);
        s_w[dl][0][tx] = wgt0 * iw;
        s_w[dl][1][tx] = wgt1 * iw;
    }
    __syncthreads();

    float* op = out + (g * D_ + d0) * HW_ + p;
#pragma unroll
    for (int dl = 0; dl < DBLK_; dl++) {
        op[dl * HW_] = fmaf(s_w[dl][0][tx], v0[dl], s_w[dl][1][tx] * v1[dl]);
    }
}

// ---------------------------------------------------------------------------
// Launch
// ---------------------------------------------------------------------------
extern "C" void kernel_launch(void* const* d_in, const int* in_sizes, int n_in,
                              void* d_out, int out_size) {
    const float* ref_feature = (const float*)d_in[0];
    const float* src_features = (const float*)d_in[1];
    const float* ref_proj = (const float*)d_in[2];
    const float* src_projs = (const float*)d_in[3];
    const float* depth_hypos = (const float*)d_in[4];
    const float* w1 = (const float*)d_in[5];
    const float* bn_gamma = (const float*)d_in[6];
    const float* bn_beta = (const float*)d_in[7];
    const float* bn_mean = (const float*)d_in[8];
    const float* bn_var = (const float*)d_in[9];
    const float* w2 = (const float*)d_in[10];
    const float* b2 = (const float*)d_in[11];
    float* out = (float*)d_out;

    prep_all_kernel<<<(T2_ + 255) / 256, 256>>>(
        ref_feature, src_features, ref_proj, src_projs, depth_hypos, w1,
        bn_gamma, bn_beta, bn_mean, bn_var, w2, b2);

    dim3 grid(W_ / 32, H_, D_ / DBLK_);
    dim3 block(32, 8);
    fuse_kernel<<<grid, block>>>(depth_hypos, out);
}

// round 12
// speedup vs baseline: 1.3113x; 1.0965x over previous
#include <cuda_runtime.h>
#include <math.h>

// Problem shape (fixed by the dataset)
#define W_ 160
#define H_ 128
#define C_ 32
#define G_ 8
#define D_ 48
#define S_ 2
#define HW_ (H_ * W_)
#define DBLK_ 4
#define NDB_ (D_ / DBLK_)

#define SNAP_ 3e-5f
#define LOG2E_ 1.44269504088896340736f

// Scratch (no cudaMalloc allowed)
__device__ float4 g_ref4[G_ * HW_];          // ref softmax, channel-packed
__device__ float4 g_src4[S_ * G_ * HW_];     // src features, channel-packed
__device__ float g_rot[S_][9];
__device__ float g_trans[S_][3];
__device__ float g_w1[G_];
__device__ float g_aff[4];  // s1, c1, w2, b2
// Fast-geometry tables (valid when g_fast != 0)
__device__ int    g_fast;
__device__ int    g_kb[S_][NDB_];
__device__ float4 g_w3[S_][D_];

typedef unsigned long long u64;

__device__ __forceinline__ float ex2f(float x) {
    float y; asm("ex2.approx.f32 %0, %1;" : "=f"(y) : "f"(x)); return y;
}
__device__ __forceinline__ u64 pk2(float a, float b) {
    u64 r; asm("mov.b64 %0, {%1, %2};" : "=l"(r) : "f"(a), "f"(b)); return r;
}
__device__ __forceinline__ void upk2(u64 v, float& a, float& b) {
    asm("mov.b64 {%0, %1}, %2;" : "=f"(a), "=f"(b) : "l"(v));
}
__device__ __forceinline__ u64 fma2(u64 a, u64 b, u64 c) {
    u64 r; asm("fma.rn.f32x2 %0, %1, %2, %3;" : "=l"(r) : "l"(a), "l"(b), "l"(c)); return r;
}
__device__ __forceinline__ u64 mul2(u64 a, u64 b) {
    u64 r; asm("mul.rn.f32x2 %0, %1, %2;" : "=l"(r) : "l"(a), "l"(b)); return r;
}

// ---------------------------------------------------------------------------
// Prep
// ---------------------------------------------------------------------------
#define T1_ (S_ * G_ * HW_)
#define T2_ (T1_ + G_ * HW_)

__global__ __launch_bounds__(256) void prep_all_kernel(
    const float* __restrict__ ref_feature,
    const float* __restrict__ srcF,
    const float* __restrict__ ref_proj,
    const float* __restrict__ src_projs,
    const float* __restrict__ depths,
    const float* __restrict__ w1,
    const float* __restrict__ bn_gamma,
    const float* __restrict__ bn_beta,
    const float* __restrict__ bn_mean,
    const float* __restrict__ bn_var,
    const float* __restrict__ w2,
    const float* __restrict__ b2) {
    int t = blockIdx.x * blockDim.x + threadIdx.x;

    if (blockIdx.x == 0) {
        if (threadIdx.x == 0) {
            float a[4][8];
            for (int i = 0; i < 4; i++)
                for (int j = 0; j < 4; j++) {
                    a[i][j] = ref_proj[i * 4 + j];
                    a[i][4 + j] = (i == j) ? 1.0f : 0.0f;
                }
            for (int col = 0; col < 4; col++) {
                int piv = col;
                float best = fabsf(a[col][col]);
                for (int r = col + 1; r < 4; r++) {
                    float v = fabsf(a[r][col]);
                    if (v > best) { best = v; piv = r; }
                }
                if (piv != col)
                    for (int j = 0; j < 8; j++) {
                        float tmp = a[col][j]; a[col][j] = a[piv][j]; a[piv][j] = tmp;
                    }
                float inv = 1.0f / a[col][col];
                for (int j = 0; j < 8; j++) a[col][j] *= inv;
                for (int r = 0; r < 4; r++) {
                    if (r == col) continue;
                    float f = a[r][col];
                    for (int j = 0; j < 8; j++) a[r][j] -= f * a[col][j];
                }
            }
            for (int s = 0; s < S_; s++) {
                const float* sp = src_projs + s * 16;
                for (int i = 0; i < 3; i++) {
                    float pr[4];
                    for (int j = 0; j < 4; j++) {
                        float acc = 0.0f;
                        for (int k = 0; k < 4; k++)
                            acc += sp[i * 4 + k] * a[k][4 + j];
                        pr[j] = acc;
                    }
                    g_rot[s][i * 3 + 0] = pr[0];
                    g_rot[s][i * 3 + 1] = pr[1];
                    g_rot[s][i * 3 + 2] = pr[2];
                    g_trans[s][i] = pr[3];
                }
            }
            for (int g = 0; g < G_; g++) g_w1[g] = w1[g];
            float s1 = bn_gamma[0] * rsqrtf(bn_var[0] + 1e-5f);
            float c1 = bn_beta[0] - bn_mean[0] * s1;
            g_aff[0] = s1;
            g_aff[1] = c1;
            g_aff[2] = w2[0];
            g_aff[3] = b2[0];

            bool fast = true;
            for (int s = 0; s < S_; s++) {
                for (int i = 0; i < 3; i++)
                    for (int j = 0; j < 3; j++) {
                        float expect = (i == j) ? 1.0f : 0.0f;
                        if (fabsf(g_rot[s][i * 3 + j] - expect) > 1e-3f) fast = false;
                    }
                if (fabsf(g_trans[s][1]) > 1e-3f) fast = false;
                if (fabsf(g_trans[s][2]) > 1e-3f) fast = false;
            }
            g_fast = fast ? 1 : 0;
        }
        __syncthreads();  // block-uniform
        if (threadIdx.x < S_ * D_) {
            int s = threadIdx.x / D_;
            int d = threadIdx.x % D_;
            int dblk = d / DBLK_;
            float t0 = g_trans[s][0];
            int kmin = 0x7fffffff, kd = 0;
            float wxd = 0.0f;
            for (int dl = 0; dl < DBLK_; dl++) {
                int dd = dblk * DBLK_ + dl;
                float shift = __fdividef(t0, depths[dd]);
                float fs = floorf(shift);
                float wx = shift - fs;
                if (wx < SNAP_) { wx = 0.0f; }
                else if (wx > 1.0f - SNAP_) { wx = 0.0f; fs += 1.0f; }
                int k = (int)fs;
                kmin = min(kmin, k);
                if (dd == d) { kd = k; wxd = wx; }
            }
            if ((d & (DBLK_ - 1)) == 0) g_kb[s][dblk] = kmin;
            int delta = kd - kmin;
            if (delta > 1) atomicExch(&g_fast, 0);  // fast tables invalid
            float wlo = (1.0f - wxd) * LOG2E_;
            float whi = wxd * LOG2E_;
            float4 w3 = make_float4(0.0f, 0.0f, 0.0f, 0.0f);
            if (delta == 0) { w3.x = wlo; w3.y = whi; }
            else            { w3.y = wlo; w3.z = whi; }
            g_w3[s][d] = w3;
        }
    }

    if (t < T1_) {
        int p = t % HW_;
        int sg = t / HW_;
        int s = sg / G_;
        int g = sg % G_;
        const float* b = srcF + (s * C_ + 4 * g) * HW_ + p;
        float4 v;
        v.x = b[0];
        v.y = b[HW_];
        v.z = b[2 * HW_];
        v.w = b[3 * HW_];
        g_src4[sg * HW_ + p] = v;
    } else if (t < T2_) {
        int u = t - T1_;
        int p = u % HW_;
        int g = u / HW_;
        const float* b = ref_feature + (g * 4) * HW_ + p;
        float e0 = __expf(b[0]);
        float e1 = __expf(b[HW_]);
        float e2 = __expf(b[2 * HW_]);
        float e3 = __expf(b[3 * HW_]);
        float is = __fdividef(1.0f, (e0 + e1) + (e2 + e3));
        float4 o;
        o.x = e0 * is;
        o.y = e1 * is;
        o.z = e2 * is;
        o.w = e3 * is;
        g_ref4[g * HW_ + p] = o;
    }
}

// ---------------------------------------------------------------------------
// General-geometry fallback, quarantined so its register pressure doesn't
// inflate the fast path (never executed on degenerate projections).
// ---------------------------------------------------------------------------
__device__ __noinline__ void general_body(int x, int y, int p, int g, int d0,
                                          const float* __restrict__ depths,
                                          float* v0, float* v1) {
    const float4* sb0 = g_src4 + (0 * G_ + g) * HW_;
    const float4* sb1 = g_src4 + (1 * G_ + g) * HW_;
    float4 r = g_ref4[g * HW_ + p];
    float xf = (float)x, yf = (float)y;
    for (int dl = 0; dl < DBLK_; dl++) {
        float depth = __ldg(depths + d0 + dl);
        float vv[2];
        for (int s = 0; s < S_; s++) {
            float X = fmaf(fmaf(g_rot[s][0], xf, fmaf(g_rot[s][1], yf, g_rot[s][2])), depth, g_trans[s][0]);
            float Y = fmaf(fmaf(g_rot[s][3], xf, fmaf(g_rot[s][4], yf, g_rot[s][5])), depth, g_trans[s][1]);
            float Z = fmaf(fmaf(g_rot[s][6], xf, fmaf(g_rot[s][7], yf, g_rot[s][8])), depth, g_trans[s][2]);
            float iz = __fdividef(1.0f, Z);
            float px = X * iz;
            float py = Y * iz;
            float x0f = floorf(px), y0f = floorf(py);
            float wx = px - x0f, wy = py - y0f;
            if (wx < SNAP_) { wx = 0.0f; }
            else if (wx > 1.0f - SNAP_) { wx = 0.0f; x0f += 1.0f; }
            if (wy < SNAP_) { wy = 0.0f; }
            else if (wy > 1.0f - SNAP_) { wy = 0.0f; y0f += 1.0f; }
            float vx0 = (x0f >= 0.0f && x0f <= (float)(W_ - 1)) ? LOG2E_ : 0.0f;
            float vx1 = (x0f + 1.0f >= 0.0f && x0f + 1.0f <= (float)(W_ - 1)) ? LOG2E_ : 0.0f;
            float vy0 = (y0f >= 0.0f && y0f <= (float)(H_ - 1)) ? 1.0f : 0.0f;
            float vy1 = (y0f + 1.0f >= 0.0f && y0f + 1.0f <= (float)(H_ - 1)) ? 1.0f : 0.0f;
            float wl = (1.0f - wx) * vx0, wr = wx * vx1;
            float wt = (1.0f - wy) * vy0, wb = wy * vy1;
            int xi0 = min(max((int)x0f, 0), W_ - 1);
            int yi0 = min(max((int)y0f, 0), H_ - 1);
            int xi1 = min(max((int)x0f + 1, 0), W_ - 1);
            int yi1 = min(max((int)y0f + 1, 0), H_ - 1);
            const float4* sb = (s == 0) ? sb0 : sb1;
            float4 qa = sb[yi0 * W_ + xi0];
            float4 qb = sb[yi0 * W_ + xi1];
            float4 qc = sb[yi1 * W_ + xi0];
            float4 qd = sb[yi1 * W_ + xi1];
            float w00 = wl * wt, w01 = wr * wt, w10 = wl * wb, w11 = wr * wb;
            float a0 = fmaf(w00, qa.x, fmaf(w01, qb.x, fmaf(w10, qc.x, w11 * qd.x)));
            float a1 = fmaf(w00, qa.y, fmaf(w01, qb.y, fmaf(w10, qc.y, w11 * qd.y)));
            float a2 = fmaf(w00, qa.z, fmaf(w01, qb.z, fmaf(w10, qc.z, w11 * qd.z)));
            float a3 = fmaf(w00, qa.w, fmaf(w01, qb.w, fmaf(w10, qc.w, w11 * qd.w)));
            float e0 = ex2f(a0), e1 = ex2f(a1);
            float e2 = ex2f(a2), e3 = ex2f(a3);
            float ss = (e0 + e1) + (e2 + e3);
            float num = fmaf(e0, r.x, fmaf(e1, r.y, fmaf(e2, r.z, e3 * r.w)));
            vv[s] = __fdividef(num, ss);
        }
        v0[dl] = vv[0];
        v1[dl] = vv[1];
    }
}

// ---------------------------------------------------------------------------
// Main fused kernel. Grid (W/32, H, D/4); block (32, 8).
// Fast path is s-MAJOR: source taps loaded and fully consumed one source at a
// time, halving tap register live-range -> 4 CTAs/SM.
// ---------------------------------------------------------------------------
__global__ __launch_bounds__(256, 4) void fuse_kernel(const float* __restrict__ depths,
                                                      float* __restrict__ out) {
    __shared__ float s_lin[DBLK_][2][G_][32];  // [dl][src][g][tx]
    __shared__ float s_w[DBLK_][2][32];        // [dl][src][tx] = wgt*iw

    int tx = threadIdx.x;
    int g = threadIdx.y;                  // group (warp-uniform)
    int x = blockIdx.x * 32 + tx;
    int y = blockIdx.y;
    int dblk = blockIdx.z;
    int d0 = dblk * DBLK_;
    int p = y * W_ + x;

    float v0[DBLK_], v1[DBLK_];

    if (g_fast) {
        float4 r = g_ref4[g * HW_ + p];
#pragma unroll
        for (int s = 0; s < S_; s++) {
            // Load 3 taps for this source (zeroed when out of range)
            int kb = g_kb[s][dblk];
            const ulonglong2* sp = (const ulonglong2*)(g_src4 + (s * G_ + g) * HW_ + y * W_);
            ulonglong2 q[3];
#pragma unroll
            for (int j = 0; j < 3; j++) {
                int xc = x + kb + j;
                bool valid = ((unsigned)xc < W_);
                int xi = min(max(xc, 0), W_ - 1);
                ulonglong2 qq = sp[xi];
                q[j].x = valid ? qq.x : 0ull;
                q[j].y = valid ? qq.y : 0ull;
            }
            float* vs = (s == 0) ? v0 : v1;
#pragma unroll
            for (int dl = 0; dl < DBLK_; dl++) {
                float4 w3 = g_w3[s][d0 + dl];
                u64 wa = pk2(w3.x, w3.x);
                u64 wb = pk2(w3.y, w3.y);
                u64 wc = pk2(w3.z, w3.z);
                u64 a01 = fma2(wa, q[0].x, fma2(wb, q[1].x, mul2(wc, q[2].x)));
                u64 a23 = fma2(wa, q[0].y, fma2(wb, q[1].y, mul2(wc, q[2].y)));
                float a0, a1, a2, a3;
                upk2(a01, a0, a1);
                upk2(a23, a2, a3);
                float e0 = ex2f(a0), e1 = ex2f(a1);
                float e2 = ex2f(a2), e3 = ex2f(a3);
                float ss = (e0 + e1) + (e2 + e3);
                float num = fmaf(e0, r.x, fmaf(e1, r.y, fmaf(e2, r.z, e3 * r.w)));
                vs[dl] = __fdividef(num, ss);
            }
        }
    } else {
        general_body(x, y, p, g, d0, depths, v0, v1);
    }

    // Stage per-group lin contributions; 4 reducer warps compute sigmoid
    // weights once per (x, d); all threads then scale and store.
    float w1g = g_w1[g];
#pragma unroll
    for (int dl = 0; dl < DBLK_; dl++) {
        s_lin[dl][0][g][tx] = w1g * v0[dl];
        s_lin[dl][1][g][tx] = w1g * v1[dl];
    }
    __syncthreads();
    if (g < DBLK_) {
        int dl = g;
        float L0 = 0.0f, L1 = 0.0f;
#pragma unroll
        for (int gg = 0; gg < G_; gg++) {
            L0 += s_lin[dl][0][gg][tx];
            L1 += s_lin[dl][1][gg][tx];
        }
        float s1 = g_aff[0], c1 = g_aff[1], w2c = g_aff[2], b2c = g_aff[3];
        float bn0 = fmaf(L0, s1, c1);
        float bn1 = fmaf(L1, s1, c1);
        float ac0 = fmaf(fmaxf(bn0, 0.0f), w2c, b2c);
        float ac1 = fmaf(fmaxf(bn1, 0.0f), w2c, b2c);
        float wgt0 = __fdividef(1.0f, 1.0f + __expf(-ac0));
        float wgt1 = __fdividef(1.0f, 1.0f + __expf(-ac1));
        float iw = __fdividef(1.0f, wgt0 + wgt1);
        s_w[dl][0][tx] = wgt0 * iw;
        s_w[dl][1][tx] = wgt1 * iw;
    }
    __syncthreads();

    float* op = out + (g * D_ + d0) * HW_ + p;
#pragma unroll
    for (int dl = 0; dl < DBLK_; dl++) {
        op[dl * HW_] = fmaf(s_w[dl][0][tx], v0[dl], s_w[dl][1][tx] * v1[dl]);
    }
}

// ---------------------------------------------------------------------------
// Launch
// ---------------------------------------------------------------------------
extern "C" void kernel_launch(void* const* d_in, const int* in_sizes, int n_in,
                              void* d_out, int out_size) {
    const float* ref_feature = (const float*)d_in[0];
    const float* src_features = (const float*)d_in[1];
    const float* ref_proj = (const float*)d_in[2];
    const float* src_projs = (const float*)d_in[3];
    const float* depth_hypos = (const float*)d_in[4];
    const float* w1 = (const float*)d_in[5];
    const float* bn_gamma = (const float*)d_in[6];
    const float* bn_beta = (const float*)d_in[7];
    const float* bn_mean = (const float*)d_in[8];
    const float* bn_var = (const float*)d_in[9];
    const float* w2 = (const float*)d_in[10];
    const float* b2 = (const float*)d_in[11];
    float* out = (float*)d_out;

    prep_all_kernel<<<(T2_ + 255) / 256, 256>>>(
        ref_feature, src_features, ref_proj, src_projs, depth_hypos, w1,
        bn_gamma, bn_beta, bn_mean, bn_var, w2, b2);

    dim3 grid(W_ / 32, H_, D_ / DBLK_);
    dim3 block(32, 8);
    fuse_kernel<<<grid, block>>>(depth_hypos, out);
}